// round 1
// baseline (speedup 1.0000x reference)
#include <cuda_runtime.h>
#include <math.h>

#define Bn 4096
#define Tn 16
#define Hn 512
#define FourH 2048

// ---------------- scratch (device globals; no allocation allowed) ----------------
__device__ float g_ZXPRE[(size_t)Tn * Bn * FourH];   // [t][b][2048] : x@Wx + b + t*Wt
__device__ float g_TGPRE[(size_t)Tn * Bn * Hn];      // [t][b][512]  : Tg gate (fully precomputed)
__device__ float g_MEM [(size_t)16 * Bn * Hn];       // ring of memory slots
__device__ float g_MEMA[(size_t)16 * Bn * Hn];       // ring of (slot @ Wa)
__device__ float g_Z   [(size_t)Bn * FourH];
__device__ float g_C   [(size_t)Bn * Hn];
__device__ float g_Hcur[(size_t)Bn * Hn];
__device__ float g_HB  [(size_t)Bn * Hn];
__device__ float g_HG  [(size_t)Bn * Hn];
__device__ float g_CTX [(size_t)Bn * Hn];
__device__ float g_HD1 [(size_t)Bn * 256];
__device__ float g_HD2 [(size_t)Bn * 32];
__device__ float g_Wcat1[512 * 2560];   // [Uh | Wa]
__device__ float g_Wcat2[512 * 1024];   // [Wb | Wg]
__device__ float g_Wxcat[63 * 2560];    // [Wx | WxT]
__device__ float g_s[512];
__device__ float g_sA[512];

__device__ __forceinline__ float sigm(float x) { return 1.f / (1.f + expf(-x)); }

// ---------------- prep kernels ----------------
__global__ void prep_weights(const float* __restrict__ Uh, const float* __restrict__ Wa,
                             const float* __restrict__ Wb, const float* __restrict__ Wg,
                             const float* __restrict__ Wx, const float* __restrict__ WxT) {
    int stride = gridDim.x * blockDim.x;
    int t0 = blockIdx.x * blockDim.x + threadIdx.x;
    for (int i = t0; i < 512 * 2560; i += stride) {
        int k = i / 2560, c = i - k * 2560;
        g_Wcat1[i] = (c < 2048) ? Uh[k * 2048 + c] : Wa[k * 512 + (c - 2048)];
    }
    for (int i = t0; i < 512 * 1024; i += stride) {
        int k = i >> 10, c = i & 1023;
        g_Wcat2[i] = (c < 512) ? Wb[k * 512 + c] : Wg[k * 512 + (c - 512)];
    }
    for (int i = t0; i < 63 * 2560; i += stride) {
        int k = i / 2560, c = i - k * 2560;
        g_Wxcat[i] = (c < 2048) ? Wx[k * 2048 + c] : WxT[k * 512 + (c - 2048)];
    }
}

__global__ void prep_s(const float* __restrict__ init_proj) {
    int h = threadIdx.x;
    float s = 0.f;
    for (int f = 0; f < 64; ++f) s += init_proj[f * 512 + h];
    g_s[h] = s;
}

__global__ void prep_sA(const float* __restrict__ Wa) {
    int h = threadIdx.x;
    float acc = 0.f;
    for (int k = 0; k < 512; ++k) acc += g_s[k] * Wa[k * 512 + h];
    g_sA[h] = acc;
}

__global__ void fill_mem() {
    size_t n = (size_t)15 * Bn * Hn;
    size_t stride = (size_t)gridDim.x * blockDim.x;
    for (size_t i = blockIdx.x * (size_t)blockDim.x + threadIdx.x; i < n; i += stride) {
        int h = (int)(i & 511);
        g_MEM[i]  = g_s[h];
        g_MEMA[i] = g_sA[h];
    }
}

// ---------------- pre-GEMM over all (b,t): [B*T,63] @ [Wx|WxT] ----------------
__global__ void __launch_bounds__(256) pre_gemm(const float* __restrict__ inp,
                                                const float* __restrict__ bvec,
                                                const float* __restrict__ Wt,
                                                const float* __restrict__ WtT,
                                                const float* __restrict__ bTv) {
    __shared__ float As[63][64];
    __shared__ float Bs[63][64];
    __shared__ float ts[64];
    int tid = threadIdx.x;
    int rbase = blockIdx.y * 64, cbase = blockIdx.x * 64;

    for (int idx = tid; idx < 64 * 64; idx += 256) {
        int k = idx >> 6, m = idx & 63;
        float v = inp[(size_t)(rbase + m) * 64 + k];
        if (k == 0) ts[m] = v; else As[k - 1][m] = v;
    }
    for (int idx = tid; idx < 63 * 64; idx += 256) {
        int k = idx >> 6, c = idx & 63;
        Bs[k][c] = g_Wxcat[(size_t)k * 2560 + cbase + c];
    }
    __syncthreads();

    int m0 = (tid >> 4) << 2, c0 = (tid & 15) << 2;
    float acc[4][4];
    #pragma unroll
    for (int i = 0; i < 4; ++i)
        #pragma unroll
        for (int j = 0; j < 4; ++j) acc[i][j] = 0.f;

    for (int k = 0; k < 63; ++k) {
        float4 av = *(const float4*)&As[k][m0];
        float4 bv = *(const float4*)&Bs[k][c0];
        float a[4] = {av.x, av.y, av.z, av.w};
        float bb[4] = {bv.x, bv.y, bv.z, bv.w};
        #pragma unroll
        for (int i = 0; i < 4; ++i)
            #pragma unroll
            for (int j = 0; j < 4; ++j) acc[i][j] = fmaf(a[i], bb[j], acc[i][j]);
    }

    #pragma unroll
    for (int i = 0; i < 4; ++i) {
        int r = rbase + m0 + i;
        int bi = r >> 4, ti = r & 15;
        float tv = ts[m0 + i];
        #pragma unroll
        for (int j = 0; j < 4; ++j) {
            int c = cbase + c0 + j;
            float v = acc[i][j];
            if (c < 2048) {
                v += bvec[c];
                if (c < 1536) v += tv * Wt[c];
                g_ZXPRE[((size_t)ti * Bn + bi) * 2048 + c] = v;
            } else {
                int jj = c - 2048;
                float tg = sigm(v + sigm(tv * WtT[jj]) + bTv[jj]);
                g_TGPRE[((size_t)ti * Bn + bi) * 512 + jj] = tg;
            }
        }
    }
}

// ---------------- main step GEMM: M=4096, K=512, tiles 128x64x16, double-buffered ----------------
// MODE 1: W=[Uh|Wa] N=2560: cols<2048 -> o0=Z (acc + e0=ZXPRE_t); cols>=2048 -> o1=MEMA slot
// MODE 2: W=[Wb|Wg] N=1024: cols<512 -> o0=HB (acc + e0=ba); else o1=HG
// MODE 3: W=We N=512: o0=MEMslot = tanh(acc + e0=HG[row] + e1=bh)
// MODE 4: W=W1 N=256: o0=HD1 = relu(acc + e0=b1)
template <int MODE>
__global__ void __launch_bounds__(256) gemm512(const float* __restrict__ A,
                                               const float* __restrict__ W, int N,
                                               const float* __restrict__ e0,
                                               const float* __restrict__ e1,
                                               float* __restrict__ o0,
                                               float* __restrict__ o1) {
    const int K = 512;
    __shared__ float As[2][16][128];
    __shared__ float Bs[2][16][64];

    const int tid  = threadIdx.x;
    const int mbase = blockIdx.y * 128;
    const int nbase = blockIdx.x * 64;
    const int trow = (tid >> 4) << 3;
    const int tcol = (tid & 15) << 2;
    const int aRow = tid & 63;
    const int aF4  = tid >> 6;      // 0..3
    const int bRow = tid >> 4;      // 0..15
    const int bCol = (tid & 15) << 2;

    const float* Abase = A + (size_t)mbase * K;
    const float* Wbase = W + nbase;

    float acc[8][4];
    #pragma unroll
    for (int i = 0; i < 8; ++i)
        #pragma unroll
        for (int j = 0; j < 4; ++j) acc[i][j] = 0.f;

    float4 ra0, ra1, rb;
    {
        int k0 = aF4 * 4;
        ra0 = *(const float4*)(Abase + (size_t)aRow * K + k0);
        ra1 = *(const float4*)(Abase + (size_t)(aRow + 64) * K + k0);
        rb  = *(const float4*)(Wbase + (size_t)bRow * N + bCol);
        int kb = aF4 * 4;
        As[0][kb + 0][aRow] = ra0.x; As[0][kb + 1][aRow] = ra0.y;
        As[0][kb + 2][aRow] = ra0.z; As[0][kb + 3][aRow] = ra0.w;
        As[0][kb + 0][aRow + 64] = ra1.x; As[0][kb + 1][aRow + 64] = ra1.y;
        As[0][kb + 2][aRow + 64] = ra1.z; As[0][kb + 3][aRow + 64] = ra1.w;
        *(float4*)&Bs[0][bRow][bCol] = rb;
    }
    __syncthreads();

    const int nk = K / 16;  // 32
    for (int kt = 0; kt < nk; ++kt) {
        int buf = kt & 1;
        if (kt + 1 < nk) {
            int k0 = (kt + 1) * 16 + aF4 * 4;
            ra0 = *(const float4*)(Abase + (size_t)aRow * K + k0);
            ra1 = *(const float4*)(Abase + (size_t)(aRow + 64) * K + k0);
            rb  = *(const float4*)(Wbase + (size_t)((kt + 1) * 16 + bRow) * N + bCol);
        }
        #pragma unroll
        for (int k = 0; k < 16; ++k) {
            float4 a0 = *(const float4*)&As[buf][k][trow];
            float4 a1 = *(const float4*)&As[buf][k][trow + 4];
            float4 bq = *(const float4*)&Bs[buf][k][tcol];
            float av[8] = {a0.x, a0.y, a0.z, a0.w, a1.x, a1.y, a1.z, a1.w};
            float bv[4] = {bq.x, bq.y, bq.z, bq.w};
            #pragma unroll
            for (int i = 0; i < 8; ++i)
                #pragma unroll
                for (int j = 0; j < 4; ++j)
                    acc[i][j] = fmaf(av[i], bv[j], acc[i][j]);
        }
        if (kt + 1 < nk) {
            int nb = buf ^ 1;
            int kb = aF4 * 4;
            As[nb][kb + 0][aRow] = ra0.x; As[nb][kb + 1][aRow] = ra0.y;
            As[nb][kb + 2][aRow] = ra0.z; As[nb][kb + 3][aRow] = ra0.w;
            As[nb][kb + 0][aRow + 64] = ra1.x; As[nb][kb + 1][aRow + 64] = ra1.y;
            As[nb][kb + 2][aRow + 64] = ra1.z; As[nb][kb + 3][aRow + 64] = ra1.w;
            *(float4*)&Bs[nb][bRow][bCol] = rb;
            __syncthreads();
        }
    }

    #pragma unroll
    for (int i = 0; i < 8; ++i) {
        int r = mbase + trow + i;
        #pragma unroll
        for (int j = 0; j < 4; ++j) {
            int c = nbase + tcol + j;
            float v = acc[i][j];
            if (MODE == 1) {
                if (c < 2048) o0[(size_t)r * 2048 + c] = v + e0[(size_t)r * 2048 + c];
                else          o1[(size_t)r * 512 + (c - 2048)] = v;
            } else if (MODE == 2) {
                if (c < 512)  o0[(size_t)r * 512 + c] = v + e0[c];
                else          o1[(size_t)r * 512 + (c - 512)] = v;
            } else if (MODE == 3) {
                o0[(size_t)r * 512 + c] = tanhf(v + e0[(size_t)r * 512 + c] + e1[c]);
            } else {
                o0[(size_t)r * 256 + c] = fmaxf(v + e0[c], 0.f);
            }
        }
    }
}

// ---------------- gates + cell update ----------------
__global__ void gates_k(const float* __restrict__ Z, const float* __restrict__ TG,
                        float* __restrict__ C, float* __restrict__ Hcur, int first) {
    int idx = blockIdx.x * blockDim.x + threadIdx.x;   // B*H
    int b = idx >> 9, j = idx & 511;
    const float* z = Z + (size_t)b * 2048;
    float zi = z[j], zf = z[j + 512], zo = z[j + 1024], zc = z[j + 1536];
    float ig = sigm(zi), fg = sigm(zf), og = sigm(zo), ch = tanhf(zc);
    float tg = TG[idx];
    float c = first ? (ig + tg) * ch : fmaf(fg, C[idx], (ig + tg) * ch);
    C[idx] = c;
    Hcur[idx] = og * tanhf(c);
}

// ---------------- attention over 15-slot memory ----------------
__global__ void __launch_bounds__(256) attn_k(const float* __restrict__ HB,
                                              const float* __restrict__ MEM,
                                              const float* __restrict__ MEMA,
                                              const float* __restrict__ va,
                                              float* __restrict__ CTX, int t) {
    int b = blockIdx.x, tid = threadIdx.x;
    __shared__ float sred[15][8];
    __shared__ float se[15];
    float hb0 = HB[(size_t)b * 512 + tid], hb1 = HB[(size_t)b * 512 + tid + 256];
    float va0 = va[tid], va1 = va[tid + 256];
    int lane = tid & 31, wp = tid >> 5;

    #pragma unroll
    for (int d = 0; d < 15; ++d) {
        int slot = (t + d) & 15;
        const float* ma = MEMA + ((size_t)slot * Bn + b) * 512;
        float s = va0 * tanhf(ma[tid] + hb0) + va1 * tanhf(ma[tid + 256] + hb1);
        #pragma unroll
        for (int off = 16; off; off >>= 1) s += __shfl_xor_sync(0xffffffffu, s, off);
        if (lane == 0) sred[d][wp] = s;
    }
    __syncthreads();
    if (tid < 15) {
        float e = 0.f;
        #pragma unroll
        for (int w2 = 0; w2 < 8; ++w2) e += sred[tid][w2];
        se[tid] = e;
    }
    __syncthreads();

    float mx = -1e30f;
    #pragma unroll
    for (int d = 0; d < 15; ++d) mx = fmaxf(mx, se[d]);
    float al[15], sum = 0.f;
    #pragma unroll
    for (int d = 0; d < 15; ++d) { al[d] = expf(se[d] - mx); sum += al[d]; }
    float inv = 1.f / sum;
    float c0 = 0.f, c1 = 0.f;
    #pragma unroll
    for (int d = 0; d < 15; ++d) {
        int slot = (t + d) & 15;
        const float* mm = MEM + ((size_t)slot * Bn + b) * 512;
        float a = al[d] * inv;
        c0 = fmaf(a, mm[tid], c0);
        c1 = fmaf(a, mm[tid + 256], c1);
    }
    CTX[(size_t)b * 512 + tid] = c0;
    CTX[(size_t)b * 512 + tid + 256] = c1;
}

// ---------------- head layers 2,3 ----------------
__global__ void head2_k(const float* __restrict__ HD1, const float* __restrict__ W2,
                        const float* __restrict__ b2, float* __restrict__ HD2) {
    int warp = (blockIdx.x * blockDim.x + threadIdx.x) >> 5;
    int lane = threadIdx.x & 31;
    if (warp >= Bn) return;
    const float* h = HD1 + (size_t)warp * 256;
    float acc = 0.f;
    for (int k = 0; k < 256; ++k) acc = fmaf(h[k], W2[k * 32 + lane], acc);
    HD2[(size_t)warp * 32 + lane] = fmaxf(acc + b2[lane], 0.f);
}

__global__ void head3_k(const float* __restrict__ HD2, const float* __restrict__ W3,
                        const float* __restrict__ b3, float* __restrict__ out) {
    int b = blockIdx.x * blockDim.x + threadIdx.x;
    if (b >= Bn) return;
    float a0 = b3[0], a1 = b3[1];
    const float* h = HD2 + (size_t)b * 32;
    #pragma unroll
    for (int k = 0; k < 32; ++k) {
        float hv = h[k];
        a0 = fmaf(hv, W3[k * 2 + 0], a0);
        a1 = fmaf(hv, W3[k * 2 + 1], a1);
    }
    float m = fmaxf(a0, a1);
    float e0v = expf(a0 - m), e1v = expf(a1 - m);
    float inv = 1.f / (e0v + e1v);
    out[(size_t)b * 2 + 0] = e0v * inv;
    out[(size_t)b * 2 + 1] = e1v * inv;
}

// ---------------- launcher ----------------
extern "C" void kernel_launch(void* const* d_in, const int* in_sizes, int n_in,
                              void* d_out, int out_size) {
    const float* inputs    = (const float*)d_in[0];
    const float* init_proj = (const float*)d_in[1];
    const float* Wx  = (const float*)d_in[3];
    const float* Uh  = (const float*)d_in[4];
    const float* Wt  = (const float*)d_in[5];
    const float* b   = (const float*)d_in[6];
    const float* WxT = (const float*)d_in[7];
    const float* WtT = (const float*)d_in[8];
    const float* bT  = (const float*)d_in[9];
    const float* Wa  = (const float*)d_in[10];
    const float* Wb  = (const float*)d_in[11];
    const float* va  = (const float*)d_in[12];
    const float* ba  = (const float*)d_in[13];
    const float* We  = (const float*)d_in[14];
    const float* Wg  = (const float*)d_in[15];
    const float* bh  = (const float*)d_in[16];
    const float* W1  = (const float*)d_in[17];
    const float* b1  = (const float*)d_in[18];
    const float* W2  = (const float*)d_in[19];
    const float* b2  = (const float*)d_in[20];
    const float* W3  = (const float*)d_in[21];
    const float* b3  = (const float*)d_in[22];
    float* out = (float*)d_out;

    float *ZXPRE, *TGPRE, *MEM, *MEMA, *Z, *C, *Hcur, *HB, *HG, *CTX, *HD1, *HD2, *Wcat1, *Wcat2;
    cudaGetSymbolAddress((void**)&ZXPRE, g_ZXPRE);
    cudaGetSymbolAddress((void**)&TGPRE, g_TGPRE);
    cudaGetSymbolAddress((void**)&MEM,   g_MEM);
    cudaGetSymbolAddress((void**)&MEMA,  g_MEMA);
    cudaGetSymbolAddress((void**)&Z,     g_Z);
    cudaGetSymbolAddress((void**)&C,     g_C);
    cudaGetSymbolAddress((void**)&Hcur,  g_Hcur);
    cudaGetSymbolAddress((void**)&HB,    g_HB);
    cudaGetSymbolAddress((void**)&HG,    g_HG);
    cudaGetSymbolAddress((void**)&CTX,   g_CTX);
    cudaGetSymbolAddress((void**)&HD1,   g_HD1);
    cudaGetSymbolAddress((void**)&HD2,   g_HD2);
    cudaGetSymbolAddress((void**)&Wcat1, g_Wcat1);
    cudaGetSymbolAddress((void**)&Wcat2, g_Wcat2);

    prep_weights<<<512, 256>>>(Uh, Wa, Wb, Wg, Wx, WxT);
    prep_s<<<1, 512>>>(init_proj);
    prep_sA<<<1, 512>>>(Wa);
    fill_mem<<<2048, 256>>>();
    pre_gemm<<<dim3(40, 1024), 256>>>(inputs, b, Wt, WtT, bT);

    for (int t = 0; t < 16; ++t) {
        int hslot = (t + 14) & 15;   // slot holding h_new(t-1)
        int wslot = (t + 15) & 15;   // slot where h_new(t) is appended
        if (t > 0) {
            gemm512<1><<<dim3(40, 32), 256>>>(
                MEM + (size_t)hslot * Bn * Hn, Wcat1, 2560,
                ZXPRE + (size_t)t * Bn * FourH, nullptr,
                Z, MEMA + (size_t)hslot * Bn * Hn);
        }
        gates_k<<<8192, 256>>>(t ? Z : ZXPRE, TGPRE + (size_t)t * Bn * Hn, C, Hcur, t == 0);
        gemm512<2><<<dim3(16, 32), 256>>>(Hcur, Wcat2, 1024, ba, nullptr, HB, HG);
        attn_k<<<4096, 256>>>(HB, MEM, MEMA, va, CTX, t);
        gemm512<3><<<dim3(8, 32), 256>>>(CTX, We, 512, HG, bh,
                                         MEM + (size_t)wslot * Bn * Hn, nullptr);
    }

    gemm512<4><<<dim3(4, 32), 256>>>(MEM + (size_t)14 * Bn * Hn, W1, 256, b1, nullptr, HD1, nullptr);
    head2_k<<<512, 256>>>(HD1, W2, b2, HD2);
    head3_k<<<16, 256>>>(HD2, W3, b3, out);
}

// round 3
// speedup vs baseline: 1.9182x; 1.9182x over previous
#include <cuda_runtime.h>
#include <cuda_bf16.h>
#include <math.h>
#include <stdint.h>

#define Bn 4096
#define Hn 512
#define KBIG 576
#define NBIG 3072
#define ASLOT ((size_t)Bn * KBIG)
#define STAGE_BYTES 36864        // A tile 18432 + B tile 18432 (128 rows x 144B)
#define SMEM_BYTES (2 * STAGE_BYTES)

// ---------------- device scratch ----------------
__device__ __nv_bfloat16 g_Ah[(size_t)17 * ASLOT];
__device__ __nv_bfloat16 g_Al[(size_t)17 * ASLOT];
__device__ __nv_bfloat16 g_WTbH[(size_t)NBIG * KBIG];
__device__ __nv_bfloat16 g_WTbL[(size_t)NBIG * KBIG];
__device__ __nv_bfloat16 g_WT2H[1024 * 512];
__device__ __nv_bfloat16 g_WT2L[1024 * 512];
__device__ __nv_bfloat16 g_WT3H[512 * 512];
__device__ __nv_bfloat16 g_WT3L[512 * 512];
__device__ __nv_bfloat16 g_WThH[256 * 512];
__device__ __nv_bfloat16 g_WThL[256 * 512];
__device__ float g_MEM [(size_t)16 * Bn * Hn];
__device__ float g_MEMA[(size_t)16 * Bn * Hn];
__device__ float g_Z   [(size_t)Bn * 2048];
__device__ float g_TG  [(size_t)Bn * Hn];
__device__ float g_C   [(size_t)Bn * Hn];
__device__ __nv_bfloat16 g_HcH[(size_t)Bn * Hn];
__device__ __nv_bfloat16 g_HcL[(size_t)Bn * Hn];
__device__ float g_HB  [(size_t)Bn * Hn];
__device__ float g_HG  [(size_t)Bn * Hn];
__device__ __nv_bfloat16 g_CXH[(size_t)Bn * Hn];
__device__ __nv_bfloat16 g_CXL[(size_t)Bn * Hn];
__device__ float g_HD1 [(size_t)Bn * 256];
__device__ float g_HD2 [(size_t)Bn * 32];
__device__ float g_s[512];
__device__ float g_sA[512];

__device__ __forceinline__ float sigm(float x) { return 1.f / (1.f + expf(-x)); }

__device__ __forceinline__ uint32_t smem_u32(const void* p) {
    uint32_t a;
    asm("{ .reg .u64 t; cvta.to.shared.u64 t, %1; cvt.u32.u64 %0, t; }" : "=r"(a) : "l"(p));
    return a;
}
__device__ __forceinline__ void ldm4(uint32_t* r, uint32_t a) {
    asm volatile("ldmatrix.sync.aligned.m8n8.x4.shared.b16 {%0,%1,%2,%3}, [%4];"
                 : "=r"(r[0]), "=r"(r[1]), "=r"(r[2]), "=r"(r[3]) : "r"(a));
}
__device__ __forceinline__ void mma16816(float* c, const uint32_t* a, uint32_t b0, uint32_t b1) {
    asm volatile("mma.sync.aligned.m16n8k16.row.col.f32.bf16.bf16.f32 "
                 "{%0,%1,%2,%3}, {%4,%5,%6,%7}, {%8,%9}, {%0,%1,%2,%3};"
                 : "+f"(c[0]), "+f"(c[1]), "+f"(c[2]), "+f"(c[3])
                 : "r"(a[0]), "r"(a[1]), "r"(a[2]), "r"(a[3]), "r"(b0), "r"(b1));
}
__device__ __forceinline__ void cp16(uint32_t saddr, const void* gptr) {
    asm volatile("cp.async.cg.shared.global [%0], [%1], 16;"
                 :: "r"(saddr), "l"(__cvta_generic_to_global(gptr)) : "memory");
}
__device__ __forceinline__ void cp_commit() {
    asm volatile("cp.async.commit_group;" ::: "memory");
}

// ---------------- prep kernels ----------------
__global__ void prep_weights_tc(const float* __restrict__ Uh, const float* __restrict__ Wx,
                                const float* __restrict__ Wt, const float* __restrict__ Wa,
                                const float* __restrict__ WxT, const float* __restrict__ Wb,
                                const float* __restrict__ Wg, const float* __restrict__ We,
                                const float* __restrict__ W1) {
    int stride = gridDim.x * blockDim.x;
    int t0 = blockIdx.x * blockDim.x + threadIdx.x;
    for (int i = t0; i < NBIG * KBIG; i += stride) {
        int n = i / KBIG, k = i - n * KBIG;
        float w;
        if (n < 2048) {
            if (k < 512) w = Uh[(size_t)k * 2048 + n];
            else if (k < 575) w = Wx[(size_t)(k - 512) * 2048 + n];
            else w = (n < 1536) ? Wt[n] : 0.f;
        } else if (n < 2560) {
            int j = n - 2048;
            w = (k >= 512 && k < 575) ? WxT[(size_t)(k - 512) * 512 + j] : 0.f;
        } else {
            int j = n - 2560;
            w = (k < 512) ? Wa[(size_t)k * 512 + j] : 0.f;
        }
        __nv_bfloat16 hi = __float2bfloat16(w);
        g_WTbH[i] = hi;
        g_WTbL[i] = __float2bfloat16(w - __bfloat162float(hi));
    }
    for (int i = t0; i < 1024 * 512; i += stride) {
        int n = i >> 9, k = i & 511;
        float w = (n < 512) ? Wb[(size_t)k * 512 + n] : Wg[(size_t)k * 512 + (n - 512)];
        __nv_bfloat16 hi = __float2bfloat16(w);
        g_WT2H[i] = hi;
        g_WT2L[i] = __float2bfloat16(w - __bfloat162float(hi));
    }
    for (int i = t0; i < 512 * 512; i += stride) {
        int n = i >> 9, k = i & 511;
        float w = We[(size_t)k * 512 + n];
        __nv_bfloat16 hi = __float2bfloat16(w);
        g_WT3H[i] = hi;
        g_WT3L[i] = __float2bfloat16(w - __bfloat162float(hi));
    }
    for (int i = t0; i < 256 * 512; i += stride) {
        int n = i >> 9, k = i & 511;
        float w = W1[(size_t)k * 256 + n];
        __nv_bfloat16 hi = __float2bfloat16(w);
        g_WThH[i] = hi;
        g_WThL[i] = __float2bfloat16(w - __bfloat162float(hi));
    }
}

__global__ void prep_s(const float* __restrict__ init_proj) {
    int h = threadIdx.x;
    float s = 0.f;
    for (int f = 0; f < 64; ++f) s += init_proj[f * 512 + h];
    g_s[h] = s;
}

__global__ void prep_sA(const float* __restrict__ Wa) {
    int h = threadIdx.x;
    float acc = 0.f;
    for (int k = 0; k < 512; ++k) acc += g_s[k] * Wa[k * 512 + h];
    g_sA[h] = acc;
}

__global__ void fill_mem() {
    size_t n = (size_t)15 * Bn * Hn;
    size_t stride = (size_t)gridDim.x * blockDim.x;
    for (size_t i = blockIdx.x * (size_t)blockDim.x + threadIdx.x; i < n; i += stride) {
        int h = (int)(i & 511);
        g_MEM[i]  = g_s[h];
        g_MEMA[i] = g_sA[h];
    }
}

__global__ void prep_A(const float* __restrict__ inp) {
    int stride = gridDim.x * blockDim.x;
    int t0 = blockIdx.x * blockDim.x + threadIdx.x;
    for (int i = t0; i < 16 * Bn * 64; i += stride) {
        int f0 = i & 63;
        int b = (i >> 6) & (Bn - 1);
        int t = i >> 18;
        float v = (f0 < 63) ? inp[((size_t)b * 16 + t) * 64 + 1 + f0]
                            : inp[((size_t)b * 16 + t) * 64];
        size_t idx = ((size_t)t * Bn + b) * KBIG + 512 + f0;
        __nv_bfloat16 hi = __float2bfloat16(v);
        g_Ah[idx] = hi;
        g_Al[idx] = __float2bfloat16(v - __bfloat162float(hi));
    }
    for (int i = t0; i < Bn * 512; i += stride) {
        size_t idx = (size_t)(i >> 9) * KBIG + (i & 511);
        g_Ah[idx] = __float2bfloat16(0.f);
        g_Al[idx] = __float2bfloat16(0.f);
    }
}

// ---------------- bf16 HMMA GEMM, 3-pass hi/lo via virtual-K ----------------
// block 128x128, 8 warps of 64x32, k-chunk 64, cp.async double buffer
// MODE 1: [UhWxWt|WxT|Wa]: c<2048 -> Z(+b); 2048-2559 -> TG (sigm); else MEMA
// MODE 2: [Wb|Wg]: c<512 -> HB(+ba); else HG
// MODE 3: We: h=tanh(acc+HG+bh) -> MEM slot + bf16 hi/lo into next A slot
// MODE 4: W1: HD1 = relu(acc+b1)
template <int MODE>
__global__ __launch_bounds__(256, 2)
void mma_gemm(const __nv_bfloat16* __restrict__ Ah, const __nv_bfloat16* __restrict__ Al,
              int lda, int K,
              const __nv_bfloat16* __restrict__ Bh, const __nv_bfloat16* __restrict__ Bl,
              const float* __restrict__ e0, const float* __restrict__ e1,
              float* __restrict__ o0, float* __restrict__ o1, float* __restrict__ o2,
              __nv_bfloat16* __restrict__ oh, __nv_bfloat16* __restrict__ ol,
              const float* __restrict__ inp, const float* __restrict__ WtT,
              const float* __restrict__ bT, int t) {
    extern __shared__ char smem[];
    uint32_t sb = smem_u32(smem);
    const int tid = threadIdx.x;
    const int lane = tid & 31, wid = tid >> 5;
    const int wm = wid & 1, wn = wid >> 1;
    const int gid = lane >> 2, tg = lane & 3;
    const int m0 = blockIdx.y * 128, n0 = blockIdx.x * 128;

    const int kch = K >> 6;
    const int nc = kch * 3;

    float acc[4][4][4];
    #pragma unroll
    for (int a = 0; a < 4; ++a)
        #pragma unroll
        for (int b2 = 0; b2 < 4; ++b2)
            #pragma unroll
            for (int c = 0; c < 4; ++c) acc[a][b2][c] = 0.f;

    auto copy_chunk = [&](int ch, int s) {
        int p = ch / kch, kc = (ch - p * kch) << 6;
        const __nv_bfloat16* Ap = (p == 1) ? Al : Ah;
        const __nv_bfloat16* Bp = (p == 2) ? Bl : Bh;
        uint32_t abase = sb + s * STAGE_BYTES;
        uint32_t bbase = abase + 18432;
        #pragma unroll
        for (int i = 0; i < 4; ++i) {
            int lin = tid + (i << 8);
            int r = lin >> 3;
            int c16 = (lin & 7) << 4;   // byte column within 128B of row
            cp16(abase + r * 144 + c16,
                 (const char*)(Ap + (size_t)(m0 + r) * lda + kc) + c16);
            cp16(bbase + r * 144 + c16,
                 (const char*)(Bp + (size_t)(n0 + r) * K + kc) + c16);
        }
    };

    copy_chunk(0, 0);
    cp_commit();

    const int arow = wm * 64 + (lane & 15);
    const int acol = (lane >> 4) << 4;          // 0 or 16 bytes
    const int brow = wn * 32 + (lane & 7) + ((lane >> 4) << 3);
    const int bcol = ((lane >> 3) & 1) << 4;

    for (int ch = 0; ch < nc; ++ch) {
        if (ch + 1 < nc) {
            copy_chunk(ch + 1, (ch + 1) & 1);
            cp_commit();
            asm volatile("cp.async.wait_group 1;" ::: "memory");
        } else {
            asm volatile("cp.async.wait_group 0;" ::: "memory");
        }
        __syncthreads();

        uint32_t abase = sb + (ch & 1) * STAGE_BYTES;
        uint32_t bbase = abase + 18432;
        #pragma unroll
        for (int k16 = 0; k16 < 4; ++k16) {
            int kb = k16 << 5;   // 32 bytes per k16
            uint32_t af[4][4];
            #pragma unroll
            for (int mi = 0; mi < 4; ++mi)
                ldm4(af[mi], abase + (arow + mi * 16) * 144 + kb + acol);
            #pragma unroll
            for (int ni2 = 0; ni2 < 2; ++ni2) {
                uint32_t bf[4];
                ldm4(bf, bbase + (brow + ni2 * 16) * 144 + kb + bcol);
                #pragma unroll
                for (int mi = 0; mi < 4; ++mi) {
                    mma16816(acc[mi][ni2 * 2],     af[mi], bf[0], bf[1]);
                    mma16816(acc[mi][ni2 * 2 + 1], af[mi], bf[2], bf[3]);
                }
            }
        }
        __syncthreads();
    }

    // -------- epilogue --------
    auto epi = [&](int m, int c, float x, float y) {
        if (MODE == 1) {
            if (c < 2048) {
                *(float2*)(o0 + (size_t)m * 2048 + c) = make_float2(x + e0[c], y + e0[c + 1]);
            } else if (c < 2560) {
                int j = c - 2048;
                float tv = inp[(size_t)m * 1024 + t * 64];
                *(float2*)(o1 + (size_t)m * 512 + j) =
                    make_float2(sigm(x + sigm(tv * WtT[j]) + bT[j]),
                                sigm(y + sigm(tv * WtT[j + 1]) + bT[j + 1]));
            } else {
                int j = c - 2560;
                *(float2*)(o2 + (size_t)m * 512 + j) = make_float2(x, y);
            }
        } else if (MODE == 2) {
            if (c < 512) {
                *(float2*)(o0 + (size_t)m * 512 + c) = make_float2(x + e0[c], y + e0[c + 1]);
            } else {
                int j = c - 512;
                *(float2*)(o1 + (size_t)m * 512 + j) = make_float2(x, y);
            }
        } else if (MODE == 3) {
            float h0 = tanhf(x + e0[(size_t)m * 512 + c] + e1[c]);
            float h1 = tanhf(y + e0[(size_t)m * 512 + c + 1] + e1[c + 1]);
            *(float2*)(o0 + (size_t)m * 512 + c) = make_float2(h0, h1);
            __nv_bfloat16 a0 = __float2bfloat16(h0), a1 = __float2bfloat16(h1);
            *(__nv_bfloat162*)(oh + (size_t)m * KBIG + c) = __halves2bfloat162(a0, a1);
            *(__nv_bfloat162*)(ol + (size_t)m * KBIG + c) =
                __halves2bfloat162(__float2bfloat16(h0 - __bfloat162float(a0)),
                                   __float2bfloat16(h1 - __bfloat162float(a1)));
        } else {
            *(float2*)(o0 + (size_t)m * 256 + c) =
                make_float2(fmaxf(x + e0[c], 0.f), fmaxf(y + e0[c + 1], 0.f));
        }
    };

    #pragma unroll
    for (int mi = 0; mi < 4; ++mi) {
        #pragma unroll
        for (int ni = 0; ni < 4; ++ni) {
            float* cc = acc[mi][ni];
            int m = m0 + wm * 64 + mi * 16 + gid;
            int c = n0 + wn * 32 + ni * 8 + (tg << 1);
            epi(m, c, cc[0], cc[1]);
            epi(m + 8, c, cc[2], cc[3]);
        }
    }
}

// ---------------- gates + cell update ----------------
__global__ void gates_k(const float* __restrict__ Z, const float* __restrict__ TG,
                        float* __restrict__ C,
                        __nv_bfloat16* __restrict__ HcH, __nv_bfloat16* __restrict__ HcL,
                        int first) {
    int idx = blockIdx.x * blockDim.x + threadIdx.x;
    int b = idx >> 9, j = idx & 511;
    const float* z = Z + (size_t)b * 2048;
    float zi = z[j], zf = z[j + 512], zo = z[j + 1024], zc = z[j + 1536];
    float ig = sigm(zi), fg = sigm(zf), og = sigm(zo), ch = tanhf(zc);
    float tg = TG[idx];
    float c = first ? (ig + tg) * ch : fmaf(fg, C[idx], (ig + tg) * ch);
    C[idx] = c;
    float h = og * tanhf(c);
    __nv_bfloat16 hi = __float2bfloat16(h);
    HcH[idx] = hi;
    HcL[idx] = __float2bfloat16(h - __bfloat162float(hi));
}

// ---------------- attention over 15-slot memory ----------------
__global__ void __launch_bounds__(256) attn_k(const float* __restrict__ HB,
                                              const float* __restrict__ MEM,
                                              const float* __restrict__ MEMA,
                                              const float* __restrict__ va,
                                              __nv_bfloat16* __restrict__ CXH,
                                              __nv_bfloat16* __restrict__ CXL, int t) {
    int b = blockIdx.x, tid = threadIdx.x;
    __shared__ float sred[15][8];
    __shared__ float se[15];
    float hb0 = HB[(size_t)b * 512 + tid], hb1 = HB[(size_t)b * 512 + tid + 256];
    float va0 = va[tid], va1 = va[tid + 256];
    int lane = tid & 31, wp = tid >> 5;

    #pragma unroll
    for (int d = 0; d < 15; ++d) {
        int slot = (t + d) & 15;
        const float* ma = MEMA + ((size_t)slot * Bn + b) * 512;
        float s = va0 * tanhf(ma[tid] + hb0) + va1 * tanhf(ma[tid + 256] + hb1);
        #pragma unroll
        for (int off = 16; off; off >>= 1) s += __shfl_xor_sync(0xffffffffu, s, off);
        if (lane == 0) sred[d][wp] = s;
    }
    __syncthreads();
    if (tid < 15) {
        float e = 0.f;
        #pragma unroll
        for (int w2 = 0; w2 < 8; ++w2) e += sred[tid][w2];
        se[tid] = e;
    }
    __syncthreads();

    float mx = -1e30f;
    #pragma unroll
    for (int d = 0; d < 15; ++d) mx = fmaxf(mx, se[d]);
    float al[15], sum = 0.f;
    #pragma unroll
    for (int d = 0; d < 15; ++d) { al[d] = expf(se[d] - mx); sum += al[d]; }
    float inv = 1.f / sum;
    float c0 = 0.f, c1 = 0.f;
    #pragma unroll
    for (int d = 0; d < 15; ++d) {
        int slot = (t + d) & 15;
        const float* mm = MEM + ((size_t)slot * Bn + b) * 512;
        float a = al[d] * inv;
        c0 = fmaf(a, mm[tid], c0);
        c1 = fmaf(a, mm[tid + 256], c1);
    }
    __nv_bfloat16 h0 = __float2bfloat16(c0), h1 = __float2bfloat16(c1);
    CXH[(size_t)b * 512 + tid] = h0;
    CXH[(size_t)b * 512 + tid + 256] = h1;
    CXL[(size_t)b * 512 + tid] = __float2bfloat16(c0 - __bfloat162float(h0));
    CXL[(size_t)b * 512 + tid + 256] = __float2bfloat16(c1 - __bfloat162float(h1));
}

// ---------------- head layers 2,3 ----------------
__global__ void head2_k(const float* __restrict__ HD1, const float* __restrict__ W2,
                        const float* __restrict__ b2, float* __restrict__ HD2) {
    int warp = (blockIdx.x * blockDim.x + threadIdx.x) >> 5;
    int lane = threadIdx.x & 31;
    if (warp >= Bn) return;
    const float* h = HD1 + (size_t)warp * 256;
    float acc = 0.f;
    for (int k = 0; k < 256; ++k) acc = fmaf(h[k], W2[k * 32 + lane], acc);
    HD2[(size_t)warp * 32 + lane] = fmaxf(acc + b2[lane], 0.f);
}

__global__ void head3_k(const float* __restrict__ HD2, const float* __restrict__ W3,
                        const float* __restrict__ b3, float* __restrict__ out) {
    int b = blockIdx.x * blockDim.x + threadIdx.x;
    if (b >= Bn) return;
    float a0 = b3[0], a1 = b3[1];
    const float* h = HD2 + (size_t)b * 32;
    #pragma unroll
    for (int k = 0; k < 32; ++k) {
        float hv = h[k];
        a0 = fmaf(hv, W3[k * 2 + 0], a0);
        a1 = fmaf(hv, W3[k * 2 + 1], a1);
    }
    float m = fmaxf(a0, a1);
    float e0v = expf(a0 - m), e1v = expf(a1 - m);
    float inv = 1.f / (e0v + e1v);
    out[(size_t)b * 2 + 0] = e0v * inv;
    out[(size_t)b * 2 + 1] = e1v * inv;
}

// ---------------- launcher ----------------
extern "C" void kernel_launch(void* const* d_in, const int* in_sizes, int n_in,
                              void* d_out, int out_size) {
    const float* inputs    = (const float*)d_in[0];
    const float* init_proj = (const float*)d_in[1];
    const float* Wx  = (const float*)d_in[3];
    const float* Uh  = (const float*)d_in[4];
    const float* Wt  = (const float*)d_in[5];
    const float* b   = (const float*)d_in[6];
    const float* WxT = (const float*)d_in[7];
    const float* WtT = (const float*)d_in[8];
    const float* bT  = (const float*)d_in[9];
    const float* Wa  = (const float*)d_in[10];
    const float* Wb  = (const float*)d_in[11];
    const float* va  = (const float*)d_in[12];
    const float* ba  = (const float*)d_in[13];
    const float* We  = (const float*)d_in[14];
    const float* Wg  = (const float*)d_in[15];
    const float* bh  = (const float*)d_in[16];
    const float* W1  = (const float*)d_in[17];
    const float* b1  = (const float*)d_in[18];
    const float* W2  = (const float*)d_in[19];
    const float* b2  = (const float*)d_in[20];
    const float* W3  = (const float*)d_in[21];
    const float* b3  = (const float*)d_in[22];
    float* out = (float*)d_out;

    cudaFuncSetAttribute(mma_gemm<1>, cudaFuncAttributeMaxDynamicSharedMemorySize, SMEM_BYTES);
    cudaFuncSetAttribute(mma_gemm<2>, cudaFuncAttributeMaxDynamicSharedMemorySize, SMEM_BYTES);
    cudaFuncSetAttribute(mma_gemm<3>, cudaFuncAttributeMaxDynamicSharedMemorySize, SMEM_BYTES);
    cudaFuncSetAttribute(mma_gemm<4>, cudaFuncAttributeMaxDynamicSharedMemorySize, SMEM_BYTES);

    __nv_bfloat16 *Ah, *Al, *WTbH, *WTbL, *WT2H, *WT2L, *WT3H, *WT3L, *WThH, *WThL;
    __nv_bfloat16 *HcH, *HcL, *CXH, *CXL;
    float *MEM, *MEMA, *Z, *TG, *C, *HB, *HG, *HD1, *HD2;
    cudaGetSymbolAddress((void**)&Ah, g_Ah);     cudaGetSymbolAddress((void**)&Al, g_Al);
    cudaGetSymbolAddress((void**)&WTbH, g_WTbH); cudaGetSymbolAddress((void**)&WTbL, g_WTbL);
    cudaGetSymbolAddress((void**)&WT2H, g_WT2H); cudaGetSymbolAddress((void**)&WT2L, g_WT2L);
    cudaGetSymbolAddress((void**)&WT3H, g_WT3H); cudaGetSymbolAddress((void**)&WT3L, g_WT3L);
    cudaGetSymbolAddress((void**)&WThH, g_WThH); cudaGetSymbolAddress((void**)&WThL, g_WThL);
    cudaGetSymbolAddress((void**)&MEM, g_MEM);   cudaGetSymbolAddress((void**)&MEMA, g_MEMA);
    cudaGetSymbolAddress((void**)&Z, g_Z);       cudaGetSymbolAddress((void**)&TG, g_TG);
    cudaGetSymbolAddress((void**)&C, g_C);
    cudaGetSymbolAddress((void**)&HcH, g_HcH);   cudaGetSymbolAddress((void**)&HcL, g_HcL);
    cudaGetSymbolAddress((void**)&HB, g_HB);     cudaGetSymbolAddress((void**)&HG, g_HG);
    cudaGetSymbolAddress((void**)&CXH, g_CXH);   cudaGetSymbolAddress((void**)&CXL, g_CXL);
    cudaGetSymbolAddress((void**)&HD1, g_HD1);   cudaGetSymbolAddress((void**)&HD2, g_HD2);

    prep_weights_tc<<<1024, 256>>>(Uh, Wx, Wt, Wa, WxT, Wb, Wg, We, W1);
    prep_s<<<1, 512>>>(init_proj);
    prep_sA<<<1, 512>>>(Wa);
    fill_mem<<<2048, 256>>>();
    prep_A<<<2048, 256>>>(inputs);

    for (int t = 0; t < 16; ++t) {
        int mema_slot = (t == 0) ? 15 : (t + 14) & 15;
        int wslot = (t + 15) & 15;
        mma_gemm<1><<<dim3(24, 32), 256, SMEM_BYTES>>>(
            Ah + (size_t)t * ASLOT, Al + (size_t)t * ASLOT, KBIG, KBIG,
            WTbH, WTbL, b, nullptr,
            Z, TG, MEMA + (size_t)mema_slot * Bn * Hn,
            nullptr, nullptr, inputs, WtT, bT, t);
        gates_k<<<8192, 256>>>(Z, TG, C, HcH, HcL, t == 0);
        mma_gemm<2><<<dim3(8, 32), 256, SMEM_BYTES>>>(
            HcH, HcL, 512, 512, WT2H, WT2L, ba, nullptr,
            HB, HG, nullptr, nullptr, nullptr, nullptr, nullptr, nullptr, 0);
        attn_k<<<4096, 256>>>(HB, MEM, MEMA, va, CXH, CXL, t);
        mma_gemm<3><<<dim3(4, 32), 256, SMEM_BYTES>>>(
            CXH, CXL, 512, 512, WT3H, WT3L, HG, bh,
            MEM + (size_t)wslot * Bn * Hn, nullptr, nullptr,
            Ah + (size_t)(t + 1) * ASLOT, Al + (size_t)(t + 1) * ASLOT,
            nullptr, nullptr, nullptr, 0);
    }

    mma_gemm<4><<<dim3(2, 32), 256, SMEM_BYTES>>>(
        Ah + (size_t)16 * ASLOT, Al + (size_t)16 * ASLOT, KBIG, 512,
        WThH, WThL, b1, nullptr,
        HD1, nullptr, nullptr, nullptr, nullptr, nullptr, nullptr, nullptr, 0);
    head2_k<<<512, 256>>>(HD1, W2, b2, HD2);
    head3_k<<<16, 256>>>(HD2, W3, b3, out);
}

// round 5
// speedup vs baseline: 2.6557x; 1.3845x over previous
#include <cuda_runtime.h>
#include <cuda_fp16.h>
#include <math.h>
#include <stdint.h>

#define Bn 4096
#define Hn 512
#define KBIG 576
#define NBIG 3072
#define ASLOT ((size_t)Bn * KBIG)
#define STAGE_BYTES 55296        // Ah 18432 + Al 18432 + Bh 18432 (128 rows x 144B)
#define SMEM_BYTES (2 * STAGE_BYTES)

// ---------------- device scratch ----------------
__device__ __half g_Ah[(size_t)17 * ASLOT];
__device__ __half g_Al[(size_t)17 * ASLOT];
__device__ __half g_WTbH[(size_t)NBIG * KBIG];
__device__ __half g_WT2H[1024 * 512];
__device__ __half g_WT3H[512 * 512];
__device__ __half g_WThH[256 * 512];
__device__ float g_MEM [(size_t)16 * Bn * Hn];
__device__ float g_MEMA[(size_t)16 * Bn * Hn];
__device__ float g_Z   [(size_t)Bn * 2048];
__device__ float g_TG  [(size_t)Bn * Hn];
__device__ float g_C   [(size_t)Bn * Hn];
__device__ __half g_HcH[(size_t)Bn * Hn];
__device__ __half g_HcL[(size_t)Bn * Hn];
__device__ float g_HB  [(size_t)Bn * Hn];
__device__ float g_HG  [(size_t)Bn * Hn];
__device__ __half g_CXH[(size_t)Bn * Hn];
__device__ __half g_CXL[(size_t)Bn * Hn];
__device__ float g_HD1 [(size_t)Bn * 256];
__device__ float g_HD2 [(size_t)Bn * 32];
__device__ float g_s[512];
__device__ float g_sA[512];

__device__ __forceinline__ float sigm(float x) { return 1.f / (1.f + expf(-x)); }

__device__ __forceinline__ uint32_t smem_u32(const void* p) {
    uint32_t a;
    asm("{ .reg .u64 t; cvta.to.shared.u64 t, %1; cvt.u32.u64 %0, t; }" : "=r"(a) : "l"(p));
    return a;
}
__device__ __forceinline__ void ldm4(uint32_t* r, uint32_t a) {
    asm volatile("ldmatrix.sync.aligned.m8n8.x4.shared.b16 {%0,%1,%2,%3}, [%4];"
                 : "=r"(r[0]), "=r"(r[1]), "=r"(r[2]), "=r"(r[3]) : "r"(a));
}
__device__ __forceinline__ void mma16816(float* c, const uint32_t* a, uint32_t b0, uint32_t b1) {
    asm volatile("mma.sync.aligned.m16n8k16.row.col.f32.f16.f16.f32 "
                 "{%0,%1,%2,%3}, {%4,%5,%6,%7}, {%8,%9}, {%0,%1,%2,%3};"
                 : "+f"(c[0]), "+f"(c[1]), "+f"(c[2]), "+f"(c[3])
                 : "r"(a[0]), "r"(a[1]), "r"(a[2]), "r"(a[3]), "r"(b0), "r"(b1));
}
__device__ __forceinline__ void cp16(uint32_t saddr, const void* gptr) {
    asm volatile("cp.async.cg.shared.global [%0], [%1], 16;"
                 :: "r"(saddr), "l"(__cvta_generic_to_global(gptr)) : "memory");
}
__device__ __forceinline__ void cp_commit() {
    asm volatile("cp.async.commit_group;" ::: "memory");
}

// ---------------- prep kernels ----------------
__global__ void prep_weights_tc(const float* __restrict__ Uh, const float* __restrict__ Wx,
                                const float* __restrict__ Wt, const float* __restrict__ Wa,
                                const float* __restrict__ WxT, const float* __restrict__ Wb,
                                const float* __restrict__ Wg, const float* __restrict__ We,
                                const float* __restrict__ W1) {
    int stride = gridDim.x * blockDim.x;
    int t0 = blockIdx.x * blockDim.x + threadIdx.x;
    for (int i = t0; i < NBIG * KBIG; i += stride) {
        int n = i / KBIG, k = i - n * KBIG;
        float w;
        if (n < 2048) {
            if (k < 512) w = Uh[(size_t)k * 2048 + n];
            else if (k < 575) w = Wx[(size_t)(k - 512) * 2048 + n];
            else w = (n < 1536) ? Wt[n] : 0.f;
        } else if (n < 2560) {
            int j = n - 2048;
            w = (k >= 512 && k < 575) ? WxT[(size_t)(k - 512) * 512 + j] : 0.f;
        } else {
            int j = n - 2560;
            w = (k < 512) ? Wa[(size_t)k * 512 + j] : 0.f;
        }
        g_WTbH[i] = __float2half(w);
    }
    for (int i = t0; i < 1024 * 512; i += stride) {
        int n = i >> 9, k = i & 511;
        float w = (n < 512) ? Wb[(size_t)k * 512 + n] : Wg[(size_t)k * 512 + (n - 512)];
        g_WT2H[i] = __float2half(w);
    }
    for (int i = t0; i < 512 * 512; i += stride) {
        int n = i >> 9, k = i & 511;
        g_WT3H[i] = __float2half(We[(size_t)k * 512 + n]);
    }
    for (int i = t0; i < 256 * 512; i += stride) {
        int n = i >> 9, k = i & 511;
        g_WThH[i] = __float2half(W1[(size_t)k * 256 + n]);
    }
}

__global__ void prep_s(const float* __restrict__ init_proj) {
    int h = threadIdx.x;
    float s = 0.f;
    for (int f = 0; f < 64; ++f) s += init_proj[f * 512 + h];
    g_s[h] = s;
}

__global__ void prep_sA(const float* __restrict__ Wa) {
    int h = threadIdx.x;
    float acc = 0.f;
    for (int k = 0; k < 512; ++k) acc += g_s[k] * Wa[k * 512 + h];
    g_sA[h] = acc;
}

__global__ void fill_mem() {
    size_t n = (size_t)15 * Bn * Hn;
    size_t stride = (size_t)gridDim.x * blockDim.x;
    for (size_t i = blockIdx.x * (size_t)blockDim.x + threadIdx.x; i < n; i += stride) {
        int h = (int)(i & 511);
        g_MEM[i]  = g_s[h];
        g_MEMA[i] = g_sA[h];
    }
}

__global__ void prep_A(const float* __restrict__ inp) {
    int stride = gridDim.x * blockDim.x;
    int t0 = blockIdx.x * blockDim.x + threadIdx.x;
    for (int i = t0; i < 16 * Bn * 64; i += stride) {
        int f0 = i & 63;
        int b = (i >> 6) & (Bn - 1);
        int t = i >> 18;
        float v = (f0 < 63) ? inp[((size_t)b * 16 + t) * 64 + 1 + f0]
                            : inp[((size_t)b * 16 + t) * 64];
        size_t idx = ((size_t)t * Bn + b) * KBIG + 512 + f0;
        __half hi = __float2half(v);
        g_Ah[idx] = hi;
        g_Al[idx] = __float2half(v - __half2float(hi));
    }
    for (int i = t0; i < Bn * 512; i += stride) {
        size_t idx = (size_t)(i >> 9) * KBIG + (i & 511);
        g_Ah[idx] = __float2half(0.f);
        g_Al[idx] = __float2half(0.f);
    }
}

// ---------------- fp16 HMMA GEMM, 2-pass hi/lo, pass-interleaved k-chunks ----------------
// block 128x128, 8 warps of 64x32, k-chunk 64, cp.async double buffer
// MODE 1: [UhWxWt|WxT|Wa]: c<2048 -> Z(+b); 2048-2559 -> TG (sigm); else MEMA
// MODE 2: [Wb|Wg]: c<512 -> HB(+ba); else HG
// MODE 3: We: h=tanh(acc+HG+bh) -> MEM slot + fp16 hi/lo into next A slot
// MODE 4: W1: HD1 = relu(acc+b1)
template <int MODE>
__global__ __launch_bounds__(256, 2)
void mma_gemm(const __half* __restrict__ Ah, const __half* __restrict__ Al,
              int lda, int K,
              const __half* __restrict__ Bh,
              const float* __restrict__ e0, const float* __restrict__ e1,
              float* __restrict__ o0, float* __restrict__ o1, float* __restrict__ o2,
              __half* __restrict__ oh, __half* __restrict__ ol,
              const float* __restrict__ inp, const float* __restrict__ WtT,
              const float* __restrict__ bT, int t) {
    extern __shared__ char smem[];
    uint32_t sb = smem_u32(smem);
    const int tid = threadIdx.x;
    const int lane = tid & 31, wid = tid >> 5;
    const int wm = wid & 1, wn = wid >> 1;
    const int gid = lane >> 2, tg = lane & 3;
    const int m0 = blockIdx.y * 128, n0 = blockIdx.x * 128;

    const int kch = K >> 6;

    float acc[4][4][4];
    #pragma unroll
    for (int a = 0; a < 4; ++a)
        #pragma unroll
        for (int b2 = 0; b2 < 4; ++b2)
            #pragma unroll
            for (int c = 0; c < 4; ++c) acc[a][b2][c] = 0.f;

    auto copy_chunk = [&](int ch, int s) {
        int kc = ch << 6;
        uint32_t base = sb + s * STAGE_BYTES;
        #pragma unroll
        for (int i = 0; i < 4; ++i) {
            int lin = tid + (i << 8);
            int r = lin >> 3;
            int c16 = (lin & 7) << 4;
            cp16(base + r * 144 + c16,
                 (const char*)(Ah + (size_t)(m0 + r) * lda + kc) + c16);
            cp16(base + 18432 + r * 144 + c16,
                 (const char*)(Al + (size_t)(m0 + r) * lda + kc) + c16);
            cp16(base + 36864 + r * 144 + c16,
                 (const char*)(Bh + (size_t)(n0 + r) * K + kc) + c16);
        }
    };

    copy_chunk(0, 0);
    cp_commit();

    const int arow = wm * 64 + (lane & 15);
    const int acol = (lane >> 4) << 4;
    const int brow = wn * 32 + (lane & 7) + ((lane >> 4) << 3);
    const int bcol = ((lane >> 3) & 1) << 4;

    for (int ch = 0; ch < kch; ++ch) {
        if (ch + 1 < kch) {
            copy_chunk(ch + 1, (ch + 1) & 1);
            cp_commit();
            asm volatile("cp.async.wait_group 1;" ::: "memory");
        } else {
            asm volatile("cp.async.wait_group 0;" ::: "memory");
        }
        __syncthreads();

        uint32_t abase = sb + (ch & 1) * STAGE_BYTES;
        uint32_t lbase = abase + 18432;
        uint32_t bbase = abase + 36864;
        #pragma unroll
        for (int k16 = 0; k16 < 4; ++k16) {
            int kb = k16 << 5;
            uint32_t bf[2][4];
            #pragma unroll
            for (int ni2 = 0; ni2 < 2; ++ni2)
                ldm4(bf[ni2], bbase + (brow + ni2 * 16) * 144 + kb + bcol);
            uint32_t af[4][4];
            #pragma unroll
            for (int mi = 0; mi < 4; ++mi)
                ldm4(af[mi], abase + (arow + mi * 16) * 144 + kb + acol);
            #pragma unroll
            for (int ni2 = 0; ni2 < 2; ++ni2)
                #pragma unroll
                for (int mi = 0; mi < 4; ++mi) {
                    mma16816(acc[mi][ni2 * 2],     af[mi], bf[ni2][0], bf[ni2][1]);
                    mma16816(acc[mi][ni2 * 2 + 1], af[mi], bf[ni2][2], bf[ni2][3]);
                }
            #pragma unroll
            for (int mi = 0; mi < 4; ++mi)
                ldm4(af[mi], lbase + (arow + mi * 16) * 144 + kb + acol);
            #pragma unroll
            for (int ni2 = 0; ni2 < 2; ++ni2)
                #pragma unroll
                for (int mi = 0; mi < 4; ++mi) {
                    mma16816(acc[mi][ni2 * 2],     af[mi], bf[ni2][0], bf[ni2][1]);
                    mma16816(acc[mi][ni2 * 2 + 1], af[mi], bf[ni2][2], bf[ni2][3]);
                }
        }
        __syncthreads();
    }

    // -------- epilogue --------
    auto epi = [&](int m, int c, float x, float y) {
        if (MODE == 1) {
            if (c < 2048) {
                *(float2*)(o0 + (size_t)m * 2048 + c) = make_float2(x + e0[c], y + e0[c + 1]);
            } else if (c < 2560) {
                int j = c - 2048;
                float tv = inp[(size_t)m * 1024 + t * 64];
                *(float2*)(o1 + (size_t)m * 512 + j) =
                    make_float2(sigm(x + sigm(tv * WtT[j]) + bT[j]),
                                sigm(y + sigm(tv * WtT[j + 1]) + bT[j + 1]));
            } else {
                int j = c - 2560;
                *(float2*)(o2 + (size_t)m * 512 + j) = make_float2(x, y);
            }
        } else if (MODE == 2) {
            if (c < 512) {
                *(float2*)(o0 + (size_t)m * 512 + c) = make_float2(x + e0[c], y + e0[c + 1]);
            } else {
                int j = c - 512;
                *(float2*)(o1 + (size_t)m * 512 + j) = make_float2(x, y);
            }
        } else if (MODE == 3) {
            float h0 = tanhf(x + e0[(size_t)m * 512 + c] + e1[c]);
            float h1 = tanhf(y + e0[(size_t)m * 512 + c + 1] + e1[c + 1]);
            *(float2*)(o0 + (size_t)m * 512 + c) = make_float2(h0, h1);
            __half a0 = __float2half(h0), a1 = __float2half(h1);
            *(__half2*)(oh + (size_t)m * KBIG + c) = __halves2half2(a0, a1);
            *(__half2*)(ol + (size_t)m * KBIG + c) =
                __halves2half2(__float2half(h0 - __half2float(a0)),
                               __float2half(h1 - __half2float(a1)));
        } else {
            *(float2*)(o0 + (size_t)m * 256 + c) =
                make_float2(fmaxf(x + e0[c], 0.f), fmaxf(y + e0[c + 1], 0.f));
        }
    };

    #pragma unroll
    for (int mi = 0; mi < 4; ++mi) {
        #pragma unroll
        for (int ni = 0; ni < 4; ++ni) {
            float* cc = acc[mi][ni];
            int m = m0 + wm * 64 + mi * 16 + gid;
            int c = n0 + wn * 32 + ni * 8 + (tg << 1);
            epi(m, c, cc[0], cc[1]);
            epi(m + 8, c, cc[2], cc[3]);
        }
    }
}

// ---------------- gates + cell update ----------------
__global__ void gates_k(const float* __restrict__ Z, const float* __restrict__ TG,
                        float* __restrict__ C,
                        __half* __restrict__ HcH, __half* __restrict__ HcL,
                        int first) {
    int idx = blockIdx.x * blockDim.x + threadIdx.x;
    int b = idx >> 9, j = idx & 511;
    const float* z = Z + (size_t)b * 2048;
    float zi = z[j], zf = z[j + 512], zo = z[j + 1024], zc = z[j + 1536];
    float ig = sigm(zi), fg = sigm(zf), og = sigm(zo), ch = tanhf(zc);
    float tg = TG[idx];
    float c = first ? (ig + tg) * ch : fmaf(fg, C[idx], (ig + tg) * ch);
    C[idx] = c;
    float h = og * tanhf(c);
    __half hi = __float2half(h);
    HcH[idx] = hi;
    HcL[idx] = __float2half(h - __half2float(hi));
}

// ---------------- attention over 15-slot memory ----------------
__global__ void __launch_bounds__(256) attn_k(const float* __restrict__ HB,
                                              const float* __restrict__ MEM,
                                              const float* __restrict__ MEMA,
                                              const float* __restrict__ va,
                                              __half* __restrict__ CXH,
                                              __half* __restrict__ CXL, int t) {
    int b = blockIdx.x, tid = threadIdx.x;
    __shared__ float sred[15][8];
    __shared__ float se[15];
    float hb0 = HB[(size_t)b * 512 + tid], hb1 = HB[(size_t)b * 512 + tid + 256];
    float va0 = va[tid], va1 = va[tid + 256];
    int lane = tid & 31, wp = tid >> 5;

    #pragma unroll
    for (int d = 0; d < 15; ++d) {
        int slot = (t + d) & 15;
        const float* ma = MEMA + ((size_t)slot * Bn + b) * 512;
        float s = va0 * tanhf(ma[tid] + hb0) + va1 * tanhf(ma[tid + 256] + hb1);
        #pragma unroll
        for (int off = 16; off; off >>= 1) s += __shfl_xor_sync(0xffffffffu, s, off);
        if (lane == 0) sred[d][wp] = s;
    }
    __syncthreads();
    if (tid < 15) {
        float e = 0.f;
        #pragma unroll
        for (int w2 = 0; w2 < 8; ++w2) e += sred[tid][w2];
        se[tid] = e;
    }
    __syncthreads();

    float mx = -1e30f;
    #pragma unroll
    for (int d = 0; d < 15; ++d) mx = fmaxf(mx, se[d]);
    float al[15], sum = 0.f;
    #pragma unroll
    for (int d = 0; d < 15; ++d) { al[d] = expf(se[d] - mx); sum += al[d]; }
    float inv = 1.f / sum;
    float c0 = 0.f, c1 = 0.f;
    #pragma unroll
    for (int d = 0; d < 15; ++d) {
        int slot = (t + d) & 15;
        const float* mm = MEM + ((size_t)slot * Bn + b) * 512;
        float a = al[d] * inv;
        c0 = fmaf(a, mm[tid], c0);
        c1 = fmaf(a, mm[tid + 256], c1);
    }
    __half h0 = __float2half(c0), h1 = __float2half(c1);
    CXH[(size_t)b * 512 + tid] = h0;
    CXH[(size_t)b * 512 + tid + 256] = h1;
    CXL[(size_t)b * 512 + tid] = __float2half(c0 - __half2float(h0));
    CXL[(size_t)b * 512 + tid + 256] = __float2half(c1 - __half2float(h1));
}

// ---------------- head layers 2,3 ----------------
__global__ void head2_k(const float* __restrict__ HD1, const float* __restrict__ W2,
                        const float* __restrict__ b2, float* __restrict__ HD2) {
    int warp = (blockIdx.x * blockDim.x + threadIdx.x) >> 5;
    int lane = threadIdx.x & 31;
    if (warp >= Bn) return;
    const float* h = HD1 + (size_t)warp * 256;
    float acc = 0.f;
    for (int k = 0; k < 256; ++k) acc = fmaf(h[k], W2[k * 32 + lane], acc);
    HD2[(size_t)warp * 32 + lane] = fmaxf(acc + b2[lane], 0.f);
}

__global__ void head3_k(const float* __restrict__ HD2, const float* __restrict__ W3,
                        const float* __restrict__ b3, float* __restrict__ out) {
    int b = blockIdx.x * blockDim.x + threadIdx.x;
    if (b >= Bn) return;
    float a0 = b3[0], a1 = b3[1];
    const float* h = HD2 + (size_t)b * 32;
    #pragma unroll
    for (int k = 0; k < 32; ++k) {
        float hv = h[k];
        a0 = fmaf(hv, W3[k * 2 + 0], a0);
        a1 = fmaf(hv, W3[k * 2 + 1], a1);
    }
    float m = fmaxf(a0, a1);
    float e0v = expf(a0 - m), e1v = expf(a1 - m);
    float inv = 1.f / (e0v + e1v);
    out[(size_t)b * 2 + 0] = e0v * inv;
    out[(size_t)b * 2 + 1] = e1v * inv;
}

// ---------------- launcher ----------------
extern "C" void kernel_launch(void* const* d_in, const int* in_sizes, int n_in,
                              void* d_out, int out_size) {
    const float* inputs    = (const float*)d_in[0];
    const float* init_proj = (const float*)d_in[1];
    const float* Wx  = (const float*)d_in[3];
    const float* Uh  = (const float*)d_in[4];
    const float* Wt  = (const float*)d_in[5];
    const float* b   = (const float*)d_in[6];
    const float* WxT = (const float*)d_in[7];
    const float* WtT = (const float*)d_in[8];
    const float* bT  = (const float*)d_in[9];
    const float* Wa  = (const float*)d_in[10];
    const float* Wb  = (const float*)d_in[11];
    const float* va  = (const float*)d_in[12];
    const float* ba  = (const float*)d_in[13];
    const float* We  = (const float*)d_in[14];
    const float* Wg  = (const float*)d_in[15];
    const float* bh  = (const float*)d_in[16];
    const float* W1  = (const float*)d_in[17];
    const float* b1  = (const float*)d_in[18];
    const float* W2  = (const float*)d_in[19];
    const float* b2  = (const float*)d_in[20];
    const float* W3  = (const float*)d_in[21];
    const float* b3  = (const float*)d_in[22];
    float* out = (float*)d_out;

    cudaFuncSetAttribute(mma_gemm<1>, cudaFuncAttributeMaxDynamicSharedMemorySize, SMEM_BYTES);
    cudaFuncSetAttribute(mma_gemm<2>, cudaFuncAttributeMaxDynamicSharedMemorySize, SMEM_BYTES);
    cudaFuncSetAttribute(mma_gemm<3>, cudaFuncAttributeMaxDynamicSharedMemorySize, SMEM_BYTES);
    cudaFuncSetAttribute(mma_gemm<4>, cudaFuncAttributeMaxDynamicSharedMemorySize, SMEM_BYTES);

    __half *Ah, *Al, *WTbH, *WT2H, *WT3H, *WThH, *HcH, *HcL, *CXH, *CXL;
    float *MEM, *MEMA, *Z, *TG, *C, *HB, *HG, *HD1, *HD2;
    cudaGetSymbolAddress((void**)&Ah, g_Ah);     cudaGetSymbolAddress((void**)&Al, g_Al);
    cudaGetSymbolAddress((void**)&WTbH, g_WTbH);
    cudaGetSymbolAddress((void**)&WT2H, g_WT2H);
    cudaGetSymbolAddress((void**)&WT3H, g_WT3H);
    cudaGetSymbolAddress((void**)&WThH, g_WThH);
    cudaGetSymbolAddress((void**)&MEM, g_MEM);   cudaGetSymbolAddress((void**)&MEMA, g_MEMA);
    cudaGetSymbolAddress((void**)&Z, g_Z);       cudaGetSymbolAddress((void**)&TG, g_TG);
    cudaGetSymbolAddress((void**)&C, g_C);
    cudaGetSymbolAddress((void**)&HcH, g_HcH);   cudaGetSymbolAddress((void**)&HcL, g_HcL);
    cudaGetSymbolAddress((void**)&HB, g_HB);     cudaGetSymbolAddress((void**)&HG, g_HG);
    cudaGetSymbolAddress((void**)&CXH, g_CXH);   cudaGetSymbolAddress((void**)&CXL, g_CXL);
    cudaGetSymbolAddress((void**)&HD1, g_HD1);   cudaGetSymbolAddress((void**)&HD2, g_HD2);

    prep_weights_tc<<<1024, 256>>>(Uh, Wx, Wt, Wa, WxT, Wb, Wg, We, W1);
    prep_s<<<1, 512>>>(init_proj);
    prep_sA<<<1, 512>>>(Wa);
    fill_mem<<<2048, 256>>>();
    prep_A<<<2048, 256>>>(inputs);

    for (int t = 0; t < 16; ++t) {
        int mema_slot = (t == 0) ? 15 : (t + 14) & 15;
        int wslot = (t + 15) & 15;
        // MODE 1: Ah, Al, lda, K, Bh, e0, e1, o0, o1, o2, oh, ol, inp, WtT, bT, t
        mma_gemm<1><<<dim3(24, 32), 256, SMEM_BYTES>>>(
            Ah + (size_t)t * ASLOT, Al + (size_t)t * ASLOT, KBIG, KBIG,
            WTbH,
            /*e0*/ b, /*e1*/ nullptr,
            /*o0*/ Z, /*o1*/ TG, /*o2*/ MEMA + (size_t)mema_slot * Bn * Hn,
            /*oh*/ nullptr, /*ol*/ nullptr,
            /*inp*/ inputs, /*WtT*/ WtT, /*bT*/ bT, /*t*/ t);
        gates_k<<<8192, 256>>>(Z, TG, C, HcH, HcL, t == 0);
        mma_gemm<2><<<dim3(8, 32), 256, SMEM_BYTES>>>(
            HcH, HcL, 512, 512,
            WT2H,
            /*e0*/ ba, /*e1*/ nullptr,
            /*o0*/ HB, /*o1*/ HG, /*o2*/ nullptr,
            /*oh*/ nullptr, /*ol*/ nullptr,
            /*inp*/ nullptr, /*WtT*/ nullptr, /*bT*/ nullptr, /*t*/ 0);
        attn_k<<<4096, 256>>>(HB, MEM, MEMA, va, CXH, CXL, t);
        mma_gemm<3><<<dim3(4, 32), 256, SMEM_BYTES>>>(
            CXH, CXL, 512, 512,
            WT3H,
            /*e0*/ HG, /*e1*/ bh,
            /*o0*/ MEM + (size_t)wslot * Bn * Hn, /*o1*/ nullptr, /*o2*/ nullptr,
            /*oh*/ Ah + (size_t)(t + 1) * ASLOT, /*ol*/ Al + (size_t)(t + 1) * ASLOT,
            /*inp*/ nullptr, /*WtT*/ nullptr, /*bT*/ nullptr, /*t*/ 0);
    }

    mma_gemm<4><<<dim3(2, 32), 256, SMEM_BYTES>>>(
        Ah + (size_t)16 * ASLOT, Al + (size_t)16 * ASLOT, KBIG, 512,
        WThH,
        /*e0*/ b1, /*e1*/ nullptr,
        /*o0*/ HD1, /*o1*/ nullptr, /*o2*/ nullptr,
        /*oh*/ nullptr, /*ol*/ nullptr,
        /*inp*/ nullptr, /*WtT*/ nullptr, /*bT*/ nullptr, /*t*/ 0);
    head2_k<<<512, 256>>>(HD1, W2, b2, HD2);
    head3_k<<<16, 256>>>(HD2, W3, b3, out);
}

// round 6
// speedup vs baseline: 3.7012x; 1.3937x over previous
#include <cuda_runtime.h>
#include <cuda_fp16.h>
#include <math.h>
#include <stdint.h>

#define Bn 4096
#define Hn 512
#define KBIG 576
#define NBIG 3072
#define ASLOT ((size_t)Bn * KBIG)
#define STAGE_BYTES 36864        // A tile 18432 + B tile 18432 (128 rows x 144B)
#define SMEM_BYTES (2 * STAGE_BYTES)

// ---------------- device scratch ----------------
__device__ __half g_Ah[(size_t)17 * ASLOT];          // [t][b][h(512)|x(63)|t(1)]
__device__ __half g_WTbH[(size_t)NBIG * KBIG];
__device__ __half g_WT2H[1024 * 512];
__device__ __half g_WT3H[512 * 512];
__device__ __half g_WThH[256 * 512];
__device__ __half g_MEMA16[(size_t)16 * Bn * Hn];    // slot j holds (h_j @ Wa), fp16
__device__ float g_Z   [(size_t)Bn * 2048];
__device__ float g_TG  [(size_t)Bn * Hn];
__device__ float g_C   [(size_t)Bn * Hn];
__device__ __half g_HcH[(size_t)Bn * Hn];
__device__ float g_HB  [(size_t)Bn * Hn];
__device__ float g_HG  [(size_t)Bn * Hn];
__device__ __half g_CXH[(size_t)Bn * Hn];
__device__ float g_HD1 [(size_t)Bn * 256];
__device__ float g_HD2 [(size_t)Bn * 32];
__device__ float g_s[512];
__device__ float g_sA[512];

__device__ __forceinline__ float sigm(float x) { return 1.f / (1.f + expf(-x)); }

__device__ __forceinline__ uint32_t smem_u32(const void* p) {
    uint32_t a;
    asm("{ .reg .u64 t; cvta.to.shared.u64 t, %1; cvt.u32.u64 %0, t; }" : "=r"(a) : "l"(p));
    return a;
}
__device__ __forceinline__ void ldm4(uint32_t* r, uint32_t a) {
    asm volatile("ldmatrix.sync.aligned.m8n8.x4.shared.b16 {%0,%1,%2,%3}, [%4];"
                 : "=r"(r[0]), "=r"(r[1]), "=r"(r[2]), "=r"(r[3]) : "r"(a));
}
__device__ __forceinline__ void mma16816(float* c, const uint32_t* a, uint32_t b0, uint32_t b1) {
    asm volatile("mma.sync.aligned.m16n8k16.row.col.f32.f16.f16.f32 "
                 "{%0,%1,%2,%3}, {%4,%5,%6,%7}, {%8,%9}, {%0,%1,%2,%3};"
                 : "+f"(c[0]), "+f"(c[1]), "+f"(c[2]), "+f"(c[3])
                 : "r"(a[0]), "r"(a[1]), "r"(a[2]), "r"(a[3]), "r"(b0), "r"(b1));
}
__device__ __forceinline__ void cp16(uint32_t saddr, const void* gptr) {
    asm volatile("cp.async.cg.shared.global [%0], [%1], 16;"
                 :: "r"(saddr), "l"(__cvta_generic_to_global(gptr)) : "memory");
}
__device__ __forceinline__ void cp_commit() {
    asm volatile("cp.async.commit_group;" ::: "memory");
}

// ---------------- prep kernels ----------------
__global__ void prep_weights_tc(const float* __restrict__ Uh, const float* __restrict__ Wx,
                                const float* __restrict__ Wt, const float* __restrict__ Wa,
                                const float* __restrict__ WxT, const float* __restrict__ Wb,
                                const float* __restrict__ Wg, const float* __restrict__ We,
                                const float* __restrict__ W1) {
    int stride = gridDim.x * blockDim.x;
    int t0 = blockIdx.x * blockDim.x + threadIdx.x;
    for (int i = t0; i < NBIG * KBIG; i += stride) {
        int n = i / KBIG, k = i - n * KBIG;
        float w;
        if (n < 2048) {
            if (k < 512) w = Uh[(size_t)k * 2048 + n];
            else if (k < 575) w = Wx[(size_t)(k - 512) * 2048 + n];
            else w = (n < 1536) ? Wt[n] : 0.f;
        } else if (n < 2560) {
            int j = n - 2048;
            w = (k >= 512 && k < 575) ? WxT[(size_t)(k - 512) * 512 + j] : 0.f;
        } else {
            int j = n - 2560;
            w = (k < 512) ? Wa[(size_t)k * 512 + j] : 0.f;
        }
        g_WTbH[i] = __float2half(w);
    }
    for (int i = t0; i < 1024 * 512; i += stride) {
        int n = i >> 9, k = i & 511;
        float w = (n < 512) ? Wb[(size_t)k * 512 + n] : Wg[(size_t)k * 512 + (n - 512)];
        g_WT2H[i] = __float2half(w);
    }
    for (int i = t0; i < 512 * 512; i += stride) {
        int n = i >> 9, k = i & 511;
        g_WT3H[i] = __float2half(We[(size_t)k * 512 + n]);
    }
    for (int i = t0; i < 256 * 512; i += stride) {
        int n = i >> 9, k = i & 511;
        g_WThH[i] = __float2half(W1[(size_t)k * 256 + n]);
    }
}

__global__ void prep_s(const float* __restrict__ init_proj) {
    int h = threadIdx.x;
    float s = 0.f;
    for (int f = 0; f < 64; ++f) s += init_proj[f * 512 + h];
    g_s[h] = s;
}

__global__ void prep_sA(const float* __restrict__ Wa) {
    int h = threadIdx.x;
    float acc = 0.f;
    for (int k = 0; k < 512; ++k) acc += g_s[k] * Wa[k * 512 + h];
    g_sA[h] = acc;
}

// x|t parts of all 16 A slots + zero h-part of slot 0
__global__ void prep_A(const float* __restrict__ inp) {
    int stride = gridDim.x * blockDim.x;
    int t0 = blockIdx.x * blockDim.x + threadIdx.x;
    for (int i = t0; i < 16 * Bn * 64; i += stride) {
        int f0 = i & 63;
        int b = (i >> 6) & (Bn - 1);
        int t = i >> 18;
        float v = (f0 < 63) ? inp[((size_t)b * 16 + t) * 64 + 1 + f0]
                            : inp[((size_t)b * 16 + t) * 64];
        g_Ah[((size_t)t * Bn + b) * KBIG + 512 + f0] = __float2half(v);
    }
    for (int i = t0; i < Bn * 512; i += stride) {
        g_Ah[(size_t)(i >> 9) * KBIG + (i & 511)] = __float2half(0.f);
    }
}

// ---------------- fp16 HMMA GEMM, single pass ----------------
// block 128x128, 8 warps of 64x32, k-chunk 64, cp.async double buffer
// MODE 1: [UhWxWt|WxT|Wa]: c<2048 -> Z(+b); 2048-2559 -> TG (sigm); else MEMA16 slot (fp16)
// MODE 2: [Wb|Wg]: c<512 -> HB(+ba); else HG
// MODE 3: We: h=tanh(acc+HG+bh) -> fp16 into next A slot h-part
// MODE 4: W1: HD1 = relu(acc+b1)
template <int MODE>
__global__ __launch_bounds__(256, 2)
void mma_gemm(const __half* __restrict__ A, int lda, int K,
              const __half* __restrict__ Bh,
              const float* __restrict__ e0, const float* __restrict__ e1,
              float* __restrict__ o0, float* __restrict__ o1,
              __half* __restrict__ o2h, __half* __restrict__ oh,
              const float* __restrict__ inp, const float* __restrict__ WtT,
              const float* __restrict__ bT, int t) {
    extern __shared__ char smem[];
    uint32_t sb = smem_u32(smem);
    const int tid = threadIdx.x;
    const int lane = tid & 31, wid = tid >> 5;
    const int wm = wid & 1, wn = wid >> 1;
    const int gid = lane >> 2, tg = lane & 3;
    const int m0 = blockIdx.y * 128, n0 = blockIdx.x * 128;

    const int kch = K >> 6;

    float acc[4][4][4];
    #pragma unroll
    for (int a = 0; a < 4; ++a)
        #pragma unroll
        for (int b2 = 0; b2 < 4; ++b2)
            #pragma unroll
            for (int c = 0; c < 4; ++c) acc[a][b2][c] = 0.f;

    auto copy_chunk = [&](int ch, int s) {
        int kc = ch << 6;
        uint32_t base = sb + s * STAGE_BYTES;
        #pragma unroll
        for (int i = 0; i < 4; ++i) {
            int lin = tid + (i << 8);
            int r = lin >> 3;
            int c16 = (lin & 7) << 4;
            cp16(base + r * 144 + c16,
                 (const char*)(A + (size_t)(m0 + r) * lda + kc) + c16);
            cp16(base + 18432 + r * 144 + c16,
                 (const char*)(Bh + (size_t)(n0 + r) * K + kc) + c16);
        }
    };

    copy_chunk(0, 0);
    cp_commit();

    const int arow = wm * 64 + (lane & 15);
    const int acol = (lane >> 4) << 4;
    const int brow = wn * 32 + (lane & 7) + ((lane >> 4) << 3);
    const int bcol = ((lane >> 3) & 1) << 4;

    for (int ch = 0; ch < kch; ++ch) {
        if (ch + 1 < kch) {
            copy_chunk(ch + 1, (ch + 1) & 1);
            cp_commit();
            asm volatile("cp.async.wait_group 1;" ::: "memory");
        } else {
            asm volatile("cp.async.wait_group 0;" ::: "memory");
        }
        __syncthreads();

        uint32_t abase = sb + (ch & 1) * STAGE_BYTES;
        uint32_t bbase = abase + 18432;
        #pragma unroll
        for (int k16 = 0; k16 < 4; ++k16) {
            int kb = k16 << 5;
            uint32_t bf[2][4];
            #pragma unroll
            for (int ni2 = 0; ni2 < 2; ++ni2)
                ldm4(bf[ni2], bbase + (brow + ni2 * 16) * 144 + kb + bcol);
            uint32_t af[4][4];
            #pragma unroll
            for (int mi = 0; mi < 4; ++mi)
                ldm4(af[mi], abase + (arow + mi * 16) * 144 + kb + acol);
            #pragma unroll
            for (int ni2 = 0; ni2 < 2; ++ni2)
                #pragma unroll
                for (int mi = 0; mi < 4; ++mi) {
                    mma16816(acc[mi][ni2 * 2],     af[mi], bf[ni2][0], bf[ni2][1]);
                    mma16816(acc[mi][ni2 * 2 + 1], af[mi], bf[ni2][2], bf[ni2][3]);
                }
        }
        __syncthreads();
    }

    // -------- epilogue --------
    auto epi = [&](int m, int c, float x, float y) {
        if (MODE == 1) {
            if (c < 2048) {
                *(float2*)(o0 + (size_t)m * 2048 + c) = make_float2(x + e0[c], y + e0[c + 1]);
            } else if (c < 2560) {
                int j = c - 2048;
                float tv = inp[(size_t)m * 1024 + t * 64];
                *(float2*)(o1 + (size_t)m * 512 + j) =
                    make_float2(sigm(x + sigm(tv * WtT[j]) + bT[j]),
                                sigm(y + sigm(tv * WtT[j + 1]) + bT[j + 1]));
            } else {
                int j = c - 2560;
                *(__half2*)(o2h + (size_t)m * 512 + j) =
                    __halves2half2(__float2half(x), __float2half(y));
            }
        } else if (MODE == 2) {
            if (c < 512) {
                *(float2*)(o0 + (size_t)m * 512 + c) = make_float2(x + e0[c], y + e0[c + 1]);
            } else {
                int j = c - 512;
                *(float2*)(o1 + (size_t)m * 512 + j) = make_float2(x, y);
            }
        } else if (MODE == 3) {
            float h0 = tanhf(x + e0[(size_t)m * 512 + c] + e1[c]);
            float h1 = tanhf(y + e0[(size_t)m * 512 + c + 1] + e1[c + 1]);
            *(__half2*)(oh + (size_t)m * KBIG + c) =
                __halves2half2(__float2half(h0), __float2half(h1));
        } else {
            *(float2*)(o0 + (size_t)m * 256 + c) =
                make_float2(fmaxf(x + e0[c], 0.f), fmaxf(y + e0[c + 1], 0.f));
        }
    };

    #pragma unroll
    for (int mi = 0; mi < 4; ++mi) {
        #pragma unroll
        for (int ni = 0; ni < 4; ++ni) {
            float* cc = acc[mi][ni];
            int m = m0 + wm * 64 + mi * 16 + gid;
            int c = n0 + wn * 32 + ni * 8 + (tg << 1);
            epi(m, c, cc[0], cc[1]);
            epi(m + 8, c, cc[2], cc[3]);
        }
    }
}

// ---------------- gates + cell update ----------------
__global__ void gates_k(const float* __restrict__ Z, const float* __restrict__ TG,
                        float* __restrict__ C, __half* __restrict__ HcH, int first) {
    int idx = blockIdx.x * blockDim.x + threadIdx.x;
    int b = idx >> 9, j = idx & 511;
    const float* z = Z + (size_t)b * 2048;
    float zi = z[j], zf = z[j + 512], zo = z[j + 1024], zc = z[j + 1536];
    float ig = sigm(zi), fg = sigm(zf), og = sigm(zo), ch = tanhf(zc);
    float tg = TG[idx];
    float c = first ? (ig + tg) * ch : fmaf(fg, C[idx], (ig + tg) * ch);
    C[idx] = c;
    HcH[idx] = __float2half(og * tanhf(c));
}

// ---------------- attention over 15-slot memory (fp16 mem, fp32 math) ----------------
// mem slot d at step t = h_j with j = t-15+d; j<0 -> init vector s.
// h_j (j>=0) lives in A slot j+1 h-part (fp16); (h_j @ Wa) lives in g_MEMA16[j].
__global__ void __launch_bounds__(256) attn_k(const float* __restrict__ HB,
                                              const float* __restrict__ va,
                                              __half* __restrict__ CXH, int t) {
    int b = blockIdx.x, tid = threadIdx.x;
    __shared__ float sred[15][8];
    __shared__ float se[15];
    float hb0 = HB[(size_t)b * 512 + tid], hb1 = HB[(size_t)b * 512 + tid + 256];
    float va0 = va[tid], va1 = va[tid + 256];
    int lane = tid & 31, wp = tid >> 5;

    #pragma unroll
    for (int d = 0; d < 15; ++d) {
        int j = t - 15 + d;
        float ma0, ma1;
        if (j < 0) {
            ma0 = g_sA[tid]; ma1 = g_sA[tid + 256];
        } else {
            const __half* ma = g_MEMA16 + ((size_t)j * Bn + b) * 512;
            ma0 = __half2float(ma[tid]); ma1 = __half2float(ma[tid + 256]);
        }
        float s = va0 * tanhf(ma0 + hb0) + va1 * tanhf(ma1 + hb1);
        #pragma unroll
        for (int off = 16; off; off >>= 1) s += __shfl_xor_sync(0xffffffffu, s, off);
        if (lane == 0) sred[d][wp] = s;
    }
    __syncthreads();
    if (tid < 15) {
        float e = 0.f;
        #pragma unroll
        for (int w2 = 0; w2 < 8; ++w2) e += sred[tid][w2];
        se[tid] = e;
    }
    __syncthreads();

    float mx = -1e30f;
    #pragma unroll
    for (int d = 0; d < 15; ++d) mx = fmaxf(mx, se[d]);
    float al[15], sum = 0.f;
    #pragma unroll
    for (int d = 0; d < 15; ++d) { al[d] = expf(se[d] - mx); sum += al[d]; }
    float inv = 1.f / sum;
    float c0 = 0.f, c1 = 0.f;
    #pragma unroll
    for (int d = 0; d < 15; ++d) {
        int j = t - 15 + d;
        float a = al[d] * inv;
        float m0, m1;
        if (j < 0) {
            m0 = g_s[tid]; m1 = g_s[tid + 256];
        } else {
            const __half* mm = g_Ah + (size_t)(j + 1) * ASLOT + (size_t)b * KBIG;
            m0 = __half2float(mm[tid]); m1 = __half2float(mm[tid + 256]);
        }
        c0 = fmaf(a, m0, c0);
        c1 = fmaf(a, m1, c1);
    }
    CXH[(size_t)b * 512 + tid] = __float2half(c0);
    CXH[(size_t)b * 512 + tid + 256] = __float2half(c1);
}

// ---------------- head layers 2,3 ----------------
__global__ void head2_k(const float* __restrict__ HD1, const float* __restrict__ W2,
                        const float* __restrict__ b2, float* __restrict__ HD2) {
    int warp = (blockIdx.x * blockDim.x + threadIdx.x) >> 5;
    int lane = threadIdx.x & 31;
    if (warp >= Bn) return;
    const float* h = HD1 + (size_t)warp * 256;
    float acc = 0.f;
    for (int k = 0; k < 256; ++k) acc = fmaf(h[k], W2[k * 32 + lane], acc);
    HD2[(size_t)warp * 32 + lane] = fmaxf(acc + b2[lane], 0.f);
}

__global__ void head3_k(const float* __restrict__ HD2, const float* __restrict__ W3,
                        const float* __restrict__ b3, float* __restrict__ out) {
    int b = blockIdx.x * blockDim.x + threadIdx.x;
    if (b >= Bn) return;
    float a0 = b3[0], a1 = b3[1];
    const float* h = HD2 + (size_t)b * 32;
    #pragma unroll
    for (int k = 0; k < 32; ++k) {
        float hv = h[k];
        a0 = fmaf(hv, W3[k * 2 + 0], a0);
        a1 = fmaf(hv, W3[k * 2 + 1], a1);
    }
    float m = fmaxf(a0, a1);
    float e0v = expf(a0 - m), e1v = expf(a1 - m);
    float inv = 1.f / (e0v + e1v);
    out[(size_t)b * 2 + 0] = e0v * inv;
    out[(size_t)b * 2 + 1] = e1v * inv;
}

// ---------------- launcher ----------------
extern "C" void kernel_launch(void* const* d_in, const int* in_sizes, int n_in,
                              void* d_out, int out_size) {
    const float* inputs    = (const float*)d_in[0];
    const float* init_proj = (const float*)d_in[1];
    const float* Wx  = (const float*)d_in[3];
    const float* Uh  = (const float*)d_in[4];
    const float* Wt  = (const float*)d_in[5];
    const float* b   = (const float*)d_in[6];
    const float* WxT = (const float*)d_in[7];
    const float* WtT = (const float*)d_in[8];
    const float* bT  = (const float*)d_in[9];
    const float* Wa  = (const float*)d_in[10];
    const float* Wb  = (const float*)d_in[11];
    const float* va  = (const float*)d_in[12];
    const float* ba  = (const float*)d_in[13];
    const float* We  = (const float*)d_in[14];
    const float* Wg  = (const float*)d_in[15];
    const float* bh  = (const float*)d_in[16];
    const float* W1  = (const float*)d_in[17];
    const float* b1  = (const float*)d_in[18];
    const float* W2  = (const float*)d_in[19];
    const float* b2  = (const float*)d_in[20];
    const float* W3  = (const float*)d_in[21];
    const float* b3  = (const float*)d_in[22];
    float* out = (float*)d_out;

    cudaFuncSetAttribute(mma_gemm<1>, cudaFuncAttributeMaxDynamicSharedMemorySize, SMEM_BYTES);
    cudaFuncSetAttribute(mma_gemm<2>, cudaFuncAttributeMaxDynamicSharedMemorySize, SMEM_BYTES);
    cudaFuncSetAttribute(mma_gemm<3>, cudaFuncAttributeMaxDynamicSharedMemorySize, SMEM_BYTES);
    cudaFuncSetAttribute(mma_gemm<4>, cudaFuncAttributeMaxDynamicSharedMemorySize, SMEM_BYTES);

    __half *Ah, *WTbH, *WT2H, *WT3H, *WThH, *MEMA16, *HcH, *CXH;
    float *Z, *TG, *C, *HB, *HG, *HD1, *HD2;
    cudaGetSymbolAddress((void**)&Ah, g_Ah);
    cudaGetSymbolAddress((void**)&WTbH, g_WTbH);
    cudaGetSymbolAddress((void**)&WT2H, g_WT2H);
    cudaGetSymbolAddress((void**)&WT3H, g_WT3H);
    cudaGetSymbolAddress((void**)&WThH, g_WThH);
    cudaGetSymbolAddress((void**)&MEMA16, g_MEMA16);
    cudaGetSymbolAddress((void**)&Z, g_Z);       cudaGetSymbolAddress((void**)&TG, g_TG);
    cudaGetSymbolAddress((void**)&C, g_C);
    cudaGetSymbolAddress((void**)&HcH, g_HcH);
    cudaGetSymbolAddress((void**)&HB, g_HB);     cudaGetSymbolAddress((void**)&HG, g_HG);
    cudaGetSymbolAddress((void**)&CXH, g_CXH);
    cudaGetSymbolAddress((void**)&HD1, g_HD1);   cudaGetSymbolAddress((void**)&HD2, g_HD2);

    prep_weights_tc<<<1024, 256>>>(Uh, Wx, Wt, Wa, WxT, Wb, Wg, We, W1);
    prep_s<<<1, 512>>>(init_proj);
    prep_sA<<<1, 512>>>(Wa);
    prep_A<<<2048, 256>>>(inputs);

    for (int t = 0; t < 16; ++t) {
        int mema_slot = (t + 15) & 15;   // slot t-1: Wa-transform of h_{t-1}; t=0 -> dummy 15
        // MODE 1: A, lda, K, Bh, e0, e1, o0, o1, o2h, oh, inp, WtT, bT, t
        mma_gemm<1><<<dim3(24, 32), 256, SMEM_BYTES>>>(
            Ah + (size_t)t * ASLOT, KBIG, KBIG,
            WTbH,
            /*e0*/ b, /*e1*/ nullptr,
            /*o0*/ Z, /*o1*/ TG,
            /*o2h*/ MEMA16 + (size_t)mema_slot * Bn * Hn, /*oh*/ nullptr,
            /*inp*/ inputs, /*WtT*/ WtT, /*bT*/ bT, /*t*/ t);
        gates_k<<<8192, 256>>>(Z, TG, C, HcH, t == 0);
        mma_gemm<2><<<dim3(8, 32), 256, SMEM_BYTES>>>(
            HcH, 512, 512,
            WT2H,
            /*e0*/ ba, /*e1*/ nullptr,
            /*o0*/ HB, /*o1*/ HG,
            /*o2h*/ nullptr, /*oh*/ nullptr,
            /*inp*/ nullptr, /*WtT*/ nullptr, /*bT*/ nullptr, /*t*/ 0);
        attn_k<<<4096, 256>>>(HB, va, CXH, t);
        mma_gemm<3><<<dim3(4, 32), 256, SMEM_BYTES>>>(
            CXH, 512, 512,
            WT3H,
            /*e0*/ HG, /*e1*/ bh,
            /*o0*/ nullptr, /*o1*/ nullptr,
            /*o2h*/ nullptr, /*oh*/ Ah + (size_t)(t + 1) * ASLOT,
            /*inp*/ nullptr, /*WtT*/ nullptr, /*bT*/ nullptr, /*t*/ 0);
    }

    mma_gemm<4><<<dim3(2, 32), 256, SMEM_BYTES>>>(
        Ah + (size_t)16 * ASLOT, KBIG, 512,
        WThH,
        /*e0*/ b1, /*e1*/ nullptr,
        /*o0*/ HD1, /*o1*/ nullptr,
        /*o2h*/ nullptr, /*oh*/ nullptr,
        /*inp*/ nullptr, /*WtT*/ nullptr, /*bT*/ nullptr, /*t*/ 0);
    head2_k<<<512, 256>>>(HD1, W2, b2, HD2);
    head3_k<<<16, 256>>>(HD2, W3, b3, out);
}